// round 1
// baseline (speedup 1.0000x reference)
#include <cuda_runtime.h>

// Problem constants (fixed by the reference)
#define B_  2
#define C_  4
#define K_  32
#define H_  96
#define W_  96
#define D_  64
#define NV  (D_*D_*D_)          // 262144 voxels per batch

// Transposed heatmaps: [b, c, h, w, k] with k contiguous (9.4 MB)
__device__ float g_hmT[B_ * C_ * H_ * W_ * K_];

// ---------------------------------------------------------------------------
// Kernel 1: transpose (B,C,K,H,W) -> (B,C,H,W,K)
// block (32,32): x = w-in-tile (read) / k (write), y = k (read) / w-in-tile (write)
// grid (W/32, H, B*C)
// ---------------------------------------------------------------------------
__global__ void vt_transpose_kernel(const float* __restrict__ hm) {
    __shared__ float tile[32][33];
    const int bc = blockIdx.z;
    const int h  = blockIdx.y;
    const int w0 = blockIdx.x * 32;

    // read: hm[bc, k=ty, h, w0+tx]  (coalesced over tx)
    tile[threadIdx.y][threadIdx.x] =
        hm[((bc * K_ + threadIdx.y) * H_ + h) * W_ + w0 + threadIdx.x];
    __syncthreads();

    // write: hmT[bc, h, w0+ty, k=tx]  (coalesced over tx)
    g_hmT[((bc * H_ + h) * W_ + w0 + threadIdx.y) * K_ + threadIdx.x] =
        tile[threadIdx.x][threadIdx.y];
}

// ---------------------------------------------------------------------------
// Kernel 2: main unprojection. One thread per voxel (b, n).
// grid = B*NV/256 blocks of 256 threads. Each block has a single b.
// ---------------------------------------------------------------------------
__global__ __launch_bounds__(256) void vt_unproject_kernel(
    const float* __restrict__ P,       // (B,C,3,4)
    const float* __restrict__ coords,  // (B,D,D,D,3)
    const float* __restrict__ conf,    // (B,C,K)
    float* __restrict__ out)           // (B,K,D,D,D)
{
    const int gid = blockIdx.x * 256 + threadIdx.x;
    const int b   = gid / NV;
    const int n   = gid - b * NV;

    __shared__ float sP[C_ * 12];
    __shared__ float sConf[C_][K_];

    const int t = threadIdx.x;
    if (t < C_ * 12) sP[t] = P[b * C_ * 12 + t];
    if (t < C_ * K_) {
        const int c = t >> 5, k = t & 31;
        float s = 0.f;
        #pragma unroll
        for (int cc = 0; cc < C_; cc++) s += conf[(b * C_ + cc) * K_ + k];
        sConf[c][k] = conf[(b * C_ + c) * K_ + k] / s;
    }
    __syncthreads();

    const float x = coords[(size_t)(b * NV + n) * 3 + 0];
    const float y = coords[(size_t)(b * NV + n) * 3 + 1];
    const float z = coords[(size_t)(b * NV + n) * 3 + 2];

    float acc[K_];
    #pragma unroll
    for (int k = 0; k < K_; k++) acc[k] = 0.f;

    #pragma unroll
    for (int c = 0; c < C_; c++) {
        const float* p = &sP[c * 12];
        const float pz = p[8] * x + p[9] * y + p[10] * z + p[11];
        if (!(pz > 0.f)) continue;   // z<=0 (or NaN) -> zero contribution

        const float inv = 1.0f / pz;
        const float u = (p[0] * x + p[1] * y + p[2] * z + p[3]) * inv;
        const float v = (p[4] * x + p[5] * y + p[6] * z + p[7]) * inv;

        // ix = u*(W-1)/H ; iy = v*(H-1)/W  (here H=W=96 -> factor 95/96)
        const float ix = u * (95.0f / 96.0f);
        const float iy = v * (95.0f / 96.0f);

        const float x0f = floorf(ix);
        const float y0f = floorf(iy);
        const float wx1 = ix - x0f, wx0 = 1.0f - wx1;
        const float wy1 = iy - y0f, wy0 = 1.0f - wy1;
        const float x1f = x0f + 1.0f;
        const float y1f = y0f + 1.0f;

        float cam[K_];
        #pragma unroll
        for (int k = 0; k < K_; k++) cam[k] = 0.f;

        const float4* base = (const float4*)&g_hmT[(size_t)((b * C_ + c) * H_) * W_ * K_];

        // corner accumulation: bounds checked on the FLOAT coords (matches ref)
        #pragma unroll
        for (int corner = 0; corner < 4; corner++) {
            const float xcf = (corner & 1) ? x1f : x0f;
            const float ycf = (corner & 2) ? y1f : y0f;
            const float w   = ((corner & 1) ? wx1 : wx0) * ((corner & 2) ? wy1 : wy0);
            if (xcf >= 0.f && xcf <= (float)(W_ - 1) &&
                ycf >= 0.f && ycf <= (float)(H_ - 1)) {
                const int xi = (int)xcf;
                const int yi = (int)ycf;
                const float4* g = base + (size_t)(yi * W_ + xi) * (K_ / 4);
                #pragma unroll
                for (int j = 0; j < K_ / 4; j++) {
                    const float4 v4 = g[j];
                    cam[4 * j + 0] += w * v4.x;
                    cam[4 * j + 1] += w * v4.y;
                    cam[4 * j + 2] += w * v4.z;
                    cam[4 * j + 3] += w * v4.w;
                }
            }
        }

        #pragma unroll
        for (int k = 0; k < K_; k++) acc[k] += cam[k] * sConf[c][k];
    }

    // out[b, k, n] — coalesced over n for each k
    #pragma unroll
    for (int k = 0; k < K_; k++)
        out[(size_t)(b * K_ + k) * NV + n] = acc[k];
}

// ---------------------------------------------------------------------------
// Launch
// ---------------------------------------------------------------------------
extern "C" void kernel_launch(void* const* d_in, const int* in_sizes, int n_in,
                              void* d_out, int out_size) {
    const float* heatmaps = (const float*)d_in[0];  // (B,C,K,H,W)
    const float* P        = (const float*)d_in[1];  // (B,C,3,4)
    const float* coords   = (const float*)d_in[2];  // (B,D,D,D,3)
    const float* conf     = (const float*)d_in[3];  // (B,C,K)
    float* out            = (float*)d_out;          // (B,K,D,D,D)

    dim3 tgrid(W_ / 32, H_, B_ * C_);
    dim3 tblk(32, 32);
    vt_transpose_kernel<<<tgrid, tblk>>>(heatmaps);

    const int total = B_ * NV;
    vt_unproject_kernel<<<total / 256, 256>>>(P, coords, conf, out);
}

// round 2
// speedup vs baseline: 1.6815x; 1.6815x over previous
#include <cuda_runtime.h>

// Problem constants (fixed by the reference)
#define B_  2
#define C_  4
#define K_  32
#define H_  96
#define W_  96
#define D_  64
#define NV  (D_*D_*D_)          // 262144 voxels per batch

// Transposed heatmaps: [b, c, h, w, k] with k contiguous (9.4 MB, L2-resident)
__device__ float g_hmT[B_ * C_ * H_ * W_ * K_];

// ---------------------------------------------------------------------------
// Kernel 1: transpose (B,C,K,H,W) -> (B,C,H,W,K)
// ---------------------------------------------------------------------------
__global__ void vt_transpose_kernel(const float* __restrict__ hm) {
    __shared__ float tile[32][33];
    const int bc = blockIdx.z;
    const int h  = blockIdx.y;
    const int w0 = blockIdx.x * 32;

    tile[threadIdx.y][threadIdx.x] =
        hm[((bc * K_ + threadIdx.y) * H_ + h) * W_ + w0 + threadIdx.x];
    __syncthreads();

    g_hmT[((bc * H_ + h) * W_ + w0 + threadIdx.y) * K_ + threadIdx.x] =
        tile[threadIdx.x][threadIdx.y];
}

// ---------------------------------------------------------------------------
// Kernel 2: main unprojection.
// 8 threads per voxel: thread group g=0..7 owns channels 4g..4g+3 (one float4).
// A warp covers 4 voxels; each corner gather is a fully-coalesced 128B row.
// Block = 256 threads = 32 voxels. Output staged through smem for coalesced STG.
// ---------------------------------------------------------------------------
__global__ __launch_bounds__(256) void vt_unproject_kernel(
    const float* __restrict__ P,       // (B,C,3,4)
    const float* __restrict__ coords,  // (B,D,D,D,3)
    const float* __restrict__ conf,    // (B,C,K)
    float* __restrict__ out)           // (B,K,D,D,D)
{
    const int tid  = threadIdx.x;
    const int g    = tid & 7;          // channel group within voxel
    const int vloc = tid >> 3;         // voxel within block, 0..31
    const int n0   = blockIdx.x * 32;  // first voxel (global over B*NV)
    const int b    = n0 / NV;
    const int n    = (n0 - b * NV) + vloc;

    __shared__ float sP[C_ * 12];
    __shared__ float sConf[C_][K_];
    __shared__ float tile[32][33];     // [voxel][channel], stride 33: conflict-free

    if (tid < C_ * 12) sP[tid] = P[b * C_ * 12 + tid];
    if (tid < C_ * K_) {
        const int c = tid >> 5, k = tid & 31;
        float s = 0.f;
        #pragma unroll
        for (int cc = 0; cc < C_; cc++) s += conf[(b * C_ + cc) * K_ + k];
        sConf[c][k] = conf[(b * C_ + c) * K_ + k] / s;
    }
    __syncthreads();

    const float x = coords[(size_t)(b * NV + n) * 3 + 0];
    const float y = coords[(size_t)(b * NV + n) * 3 + 1];
    const float z = coords[(size_t)(b * NV + n) * 3 + 2];

    float4 acc = make_float4(0.f, 0.f, 0.f, 0.f);

    #pragma unroll
    for (int c = 0; c < C_; c++) {
        const float* p = &sP[c * 12];
        const float pz = p[8] * x + p[9] * y + p[10] * z + p[11];
        if (!(pz > 0.f)) continue;   // z<=0 -> zero contribution (matches ref)

        const float inv = 1.0f / pz;
        const float u = (p[0] * x + p[1] * y + p[2] * z + p[3]) * inv;
        const float v = (p[4] * x + p[5] * y + p[6] * z + p[7]) * inv;

        // ix = u*(W-1)/H ; iy = v*(H-1)/W  (H=W=96 -> factor 95/96)
        const float ix = u * (95.0f / 96.0f);
        const float iy = v * (95.0f / 96.0f);

        const float x0f = floorf(ix);
        const float y0f = floorf(iy);
        const float wx1 = ix - x0f, wx0 = 1.0f - wx1;
        const float wy1 = iy - y0f, wy0 = 1.0f - wy1;
        const float x1f = x0f + 1.0f;
        const float y1f = y0f + 1.0f;

        float4 cam = make_float4(0.f, 0.f, 0.f, 0.f);

        // base for this (b,c): rows of K floats; this thread reads quad g
        const float4* base = (const float4*)
            &g_hmT[((size_t)(b * C_ + c) * H_ * W_) * K_];

        #pragma unroll
        for (int corner = 0; corner < 4; corner++) {
            const float xcf = (corner & 1) ? x1f : x0f;
            const float ycf = (corner & 2) ? y1f : y0f;
            const float w   = ((corner & 1) ? wx1 : wx0) * ((corner & 2) ? wy1 : wy0);
            if (xcf >= 0.f && xcf <= (float)(W_ - 1) &&
                ycf >= 0.f && ycf <= (float)(H_ - 1)) {
                const int xi = (int)xcf;
                const int yi = (int)ycf;
                // lanes g=0..7 read 8 consecutive float4 -> one 128B line
                const float4 v4 = base[(size_t)(yi * W_ + xi) * (K_ / 4) + g];
                cam.x += w * v4.x;
                cam.y += w * v4.y;
                cam.z += w * v4.z;
                cam.w += w * v4.w;
            }
        }

        acc.x += cam.x * sConf[c][4 * g + 0];
        acc.y += cam.y * sConf[c][4 * g + 1];
        acc.z += cam.z * sConf[c][4 * g + 2];
        acc.w += cam.w * sConf[c][4 * g + 3];
    }

    // stage into smem: tile[vloc][4g..4g+3]  (stride-33 scalar stores, conflict-free)
    tile[vloc][4 * g + 0] = acc.x;
    tile[vloc][4 * g + 1] = acc.y;
    tile[vloc][4 * g + 2] = acc.z;
    tile[vloc][4 * g + 3] = acc.w;
    __syncthreads();

    // coalesced writeout: 4 (k, i) pairs per thread
    const int i  = tid & 31;            // voxel index within block
    const int kb = tid >> 5;            // 0..7
    const int nbase = (n0 - b * NV);
    #pragma unroll
    for (int r = 0; r < 4; r++) {
        const int k = r * 8 + kb;
        out[(size_t)(b * K_ + k) * NV + nbase + i] = tile[i][k];
    }
}

// ---------------------------------------------------------------------------
// Launch
// ---------------------------------------------------------------------------
extern "C" void kernel_launch(void* const* d_in, const int* in_sizes, int n_in,
                              void* d_out, int out_size) {
    const float* heatmaps = (const float*)d_in[0];  // (B,C,K,H,W)
    const float* P        = (const float*)d_in[1];  // (B,C,3,4)
    const float* coords   = (const float*)d_in[2];  // (B,D,D,D,3)
    const float* conf     = (const float*)d_in[3];  // (B,C,K)
    float* out            = (float*)d_out;          // (B,K,D,D,D)

    dim3 tgrid(W_ / 32, H_, B_ * C_);
    dim3 tblk(32, 32);
    vt_transpose_kernel<<<tgrid, tblk>>>(heatmaps);

    const int nblocks = (B_ * NV) / 32;   // 32 voxels per block
    vt_unproject_kernel<<<nblocks, 256>>>(P, coords, conf, out);
}

// round 3
// speedup vs baseline: 1.9394x; 1.1534x over previous
#include <cuda_runtime.h>

// Problem constants (fixed by the reference)
#define B_  2
#define C_  4
#define K_  32
#define H_  96
#define W_  96
#define D_  64
#define NV  (D_*D_*D_)          // 262144 voxels per batch

// Transposed heatmaps: [b, c, h, w, k] with k contiguous (9.4 MB, L2-resident)
__device__ float g_hmT[B_ * C_ * H_ * W_ * K_];

typedef unsigned long long ull;

__device__ __forceinline__ float frcp_approx(float x) {
    float r; asm("rcp.approx.f32 %0, %1;" : "=f"(r) : "f"(x)); return r;
}
__device__ __forceinline__ ull pack2(float a, float b) {
    ull r; asm("mov.b64 %0, {%1, %2};" : "=l"(r) : "f"(a), "f"(b)); return r;
}
__device__ __forceinline__ void unpack2(ull v, float& a, float& b) {
    asm("mov.b64 {%0, %1}, %2;" : "=f"(a), "=f"(b) : "l"(v));
}
// d = a*b + d on packed f32x2 (sm_103a FFMA2)
__device__ __forceinline__ void ffma2(ull& d, ull a, ull b) {
    asm("fma.rn.f32x2 %0, %1, %2, %0;" : "+l"(d) : "l"(a), "l"(b));
}

// ---------------------------------------------------------------------------
// Kernel 1: transpose (B,C,K,H,W) -> (B,C,H,W,K). 8 h-rows per block.
// grid (W/32, H/8, B*C), block (32,32)
// ---------------------------------------------------------------------------
__global__ void vt_transpose_kernel(const float* __restrict__ hm) {
    __shared__ float tile[32][33];
    const int bc = blockIdx.z;
    const int w0 = blockIdx.x * 32;
    const int h0 = blockIdx.y * 8;

    #pragma unroll
    for (int hh = 0; hh < 8; hh++) {
        const int h = h0 + hh;
        tile[threadIdx.y][threadIdx.x] =
            hm[((bc * K_ + threadIdx.y) * H_ + h) * W_ + w0 + threadIdx.x];
        __syncthreads();
        g_hmT[((bc * H_ + h) * W_ + w0 + threadIdx.y) * K_ + threadIdx.x] =
            tile[threadIdx.x][threadIdx.y];
        __syncthreads();
    }
}

// ---------------------------------------------------------------------------
// Kernel 2: main unprojection.
// 8 threads per voxel: group g owns channels 4g..4g+3 (one float4).
// Warp covers 4 voxels; each corner gather is a fully-coalesced 128B row.
// All index math 32-bit; accumulation in packed f32x2.
// ---------------------------------------------------------------------------
__global__ __launch_bounds__(256) void vt_unproject_kernel(
    const float* __restrict__ P,       // (B,C,3,4)
    const float* __restrict__ coords,  // (B,D,D,D,3)
    const float* __restrict__ conf,    // (B,C,K)
    float* __restrict__ out)           // (B,K,D,D,D)
{
    const int tid  = threadIdx.x;
    const int g    = tid & 7;          // channel quad within voxel
    const int vloc = tid >> 3;         // voxel within block, 0..31
    const int b    = blockIdx.x >> 13;            // NV/32 = 8192 blocks/batch
    const int nb   = (blockIdx.x & 8191) * 32;    // base voxel within batch
    const int n    = nb + vloc;

    __shared__ float sP[C_ * 12];
    __shared__ float sConf[C_][K_];
    __shared__ float tile[32][33];

    if (tid < C_ * 12) sP[tid] = P[b * C_ * 12 + tid];
    if (tid < C_ * K_) {
        const int c = tid >> 5, k = tid & 31;
        float s = 0.f;
        #pragma unroll
        for (int cc = 0; cc < C_; cc++) s += conf[(b * C_ + cc) * K_ + k];
        sConf[c][k] = conf[(b * C_ + c) * K_ + k] / s;
    }
    __syncthreads();

    const int ci = (b * NV + n) * 3;
    const float x = coords[ci + 0];
    const float y = coords[ci + 1];
    const float z = coords[ci + 2];

    // preload this thread's packed confidences (channels 4g..4g+3, per camera)
    ull cpk[C_][2];
    #pragma unroll
    for (int c = 0; c < C_; c++) {
        const float2* cf = (const float2*)&sConf[c][4 * g];
        const float2 c0 = cf[0], c1 = cf[1];
        cpk[c][0] = pack2(c0.x, c0.y);
        cpk[c][1] = pack2(c1.x, c1.y);
    }

    ull acc0 = 0ull, acc1 = 0ull;   // packed (0.f, 0.f)

    // heatmap base for this b, as float4 rows of 8 quads; this thread reads quad g
    const float4* hb = (const float4*)&g_hmT[(b * C_) * (H_ * W_ * K_)];

    #pragma unroll
    for (int c = 0; c < C_; c++) {
        const float* p = &sP[c * 12];
        const float pz = fmaf(p[8], x, fmaf(p[9], y, fmaf(p[10], z, p[11])));
        if (!(pz > 0.f)) continue;   // z<=0 -> zero contribution (matches ref)

        const float s  = frcp_approx(pz) * (95.0f / 96.0f);
        const float un = fmaf(p[0], x, fmaf(p[1], y, fmaf(p[2], z, p[3])));
        const float vn = fmaf(p[4], x, fmaf(p[5], y, fmaf(p[6], z, p[7])));
        const float ix = un * s;     // ix = (u/z)*(W-1)/H
        const float iy = vn * s;

        const float x0f = floorf(ix), y0f = floorf(iy);
        const float x1f = x0f + 1.f, y1f = y0f + 1.f;
        const float wx1 = ix - x0f,  wy1 = iy - y0f;
        const float wx0 = 1.f - wx1, wy0 = 1.f - wy1;

        const bool bx0 = (x0f >= 0.f) & (x0f <= 95.f);
        const bool bx1 = (x1f >= 0.f) & (x1f <= 95.f);
        const bool by0 = (y0f >= 0.f) & (y0f <= 95.f);
        const bool by1 = (y1f >= 0.f) & (y1f <= 95.f);

        ull cam0 = 0ull, cam1 = 0ull;
        const float4* cb = hb + c * (H_ * W_ * K_ / 4) + g;

        #define VT_CORNER(BX, BY, XF, YF, WX, WY)                 \
            if (BX & BY) {                                        \
                const int idx = (int)fmaf(YF, 96.f, XF);          \
                const float4 v4 = cb[idx * 8];                    \
                const float wc = (WX) * (WY);                     \
                const ull wp = pack2(wc, wc);                     \
                ffma2(cam0, wp, pack2(v4.x, v4.y));               \
                ffma2(cam1, wp, pack2(v4.z, v4.w));               \
            }

        VT_CORNER(bx0, by0, x0f, y0f, wx0, wy0)
        VT_CORNER(bx1, by0, x1f, y0f, wx1, wy0)
        VT_CORNER(bx0, by1, x0f, y1f, wx0, wy1)
        VT_CORNER(bx1, by1, x1f, y1f, wx1, wy1)
        #undef VT_CORNER

        ffma2(acc0, cam0, cpk[c][0]);
        ffma2(acc1, cam1, cpk[c][1]);
    }

    // stage into smem for coalesced writeout
    float a0, a1, a2, a3;
    unpack2(acc0, a0, a1);
    unpack2(acc1, a2, a3);
    tile[vloc][4 * g + 0] = a0;
    tile[vloc][4 * g + 1] = a1;
    tile[vloc][4 * g + 2] = a2;
    tile[vloc][4 * g + 3] = a3;
    __syncthreads();

    const int i  = tid & 31;   // voxel index within block
    const int kb = tid >> 5;   // 0..7
    #pragma unroll
    for (int r = 0; r < 4; r++) {
        const int k = r * 8 + kb;
        out[(b * K_ + k) * NV + nb + i] = tile[i][k];
    }
}

// ---------------------------------------------------------------------------
// Launch
// ---------------------------------------------------------------------------
extern "C" void kernel_launch(void* const* d_in, const int* in_sizes, int n_in,
                              void* d_out, int out_size) {
    const float* heatmaps = (const float*)d_in[0];  // (B,C,K,H,W)
    const float* P        = (const float*)d_in[1];  // (B,C,3,4)
    const float* coords   = (const float*)d_in[2];  // (B,D,D,D,3)
    const float* conf     = (const float*)d_in[3];  // (B,C,K)
    float* out            = (float*)d_out;          // (B,K,D,D,D)

    dim3 tgrid(W_ / 32, H_ / 8, B_ * C_);
    dim3 tblk(32, 32);
    vt_transpose_kernel<<<tgrid, tblk>>>(heatmaps);

    const int nblocks = (B_ * NV) / 32;   // 32 voxels per block
    vt_unproject_kernel<<<nblocks, 256>>>(P, coords, conf, out);
}